// round 1
// baseline (speedup 1.0000x reference)
#include <cuda_runtime.h>
#include <math.h>

#define N_NODES 864
#define IN_F    4096
#define OUT_F   1024
#define ALPHA   0.2f
#define NEG_INF -9e15f

// ---------------- device scratch (no allocation allowed) ----------------
__device__ float g_Wh[N_NODES * OUT_F];        // [864, 1024]
__device__ float g_att1[N_NODES * N_NODES];    // [864, 864]
__device__ float g_att2[N_NODES * N_NODES];    // [864, 864]
__device__ float g_Wh1[N_NODES];
__device__ float g_Wh2[N_NODES];
__device__ float g_logits[2];
__device__ float g_wgt[2];

// ---------------- tiled SGEMM: 64x64 tile, BK=16, 4x4 per thread ----------------
// FUSED=false: C(g_Wh) = A(h)[M,K] @ B(W)[K,N]
// FUSED=true : C(out)  = elu( (w0*att1 + w1*att2)[M,K] @ g_Wh[K,N] )
template <bool FUSED>
__global__ void sgemm64_kernel(const float* __restrict__ A,
                               const float* __restrict__ B,
                               float* __restrict__ C,
                               int M, int K, int N) {
    __shared__ float As[64][17];   // padded: conflict-free column reads
    __shared__ float Bs[16][64];

    const int tid = threadIdx.x;           // 256 threads
    const int tx  = tid & 15;
    const int ty  = tid >> 4;
    const int bm  = blockIdx.y * 64;
    const int bn  = blockIdx.x * 64;

    const int arow = tid >> 2;             // 0..63
    const int acol = (tid & 3) << 2;       // 0,4,8,12
    const int brow = tid >> 4;             // 0..15
    const int bcol = (tid & 15) << 2;      // 0..60

    float w0 = 0.f, w1 = 0.f;
    if (FUSED) { w0 = g_wgt[0]; w1 = g_wgt[1]; }

    const float* Bptr = FUSED ? (const float*)g_Wh : B;
    float acc[4][4] = {};

    const int  agrow  = bm + arow;
    const bool avalid = (agrow < M);

    for (int k0 = 0; k0 < K; k0 += 16) {
        float4 av = make_float4(0.f, 0.f, 0.f, 0.f);
        if (avalid) {
            if (FUSED) {
                const float4 a1 = *(const float4*)(g_att1 + (size_t)agrow * N_NODES + k0 + acol);
                const float4 a2 = *(const float4*)(g_att2 + (size_t)agrow * N_NODES + k0 + acol);
                av.x = w0 * a1.x + w1 * a2.x;
                av.y = w0 * a1.y + w1 * a2.y;
                av.z = w0 * a1.z + w1 * a2.z;
                av.w = w0 * a1.w + w1 * a2.w;
            } else {
                av = *(const float4*)(A + (size_t)agrow * K + k0 + acol);
            }
        }
        As[arow][acol + 0] = av.x;
        As[arow][acol + 1] = av.y;
        As[arow][acol + 2] = av.z;
        As[arow][acol + 3] = av.w;

        *(float4*)&Bs[brow][bcol] =
            *(const float4*)(Bptr + (size_t)(k0 + brow) * N + bn + bcol);

        __syncthreads();

        #pragma unroll
        for (int k = 0; k < 16; k++) {
            const float a0 = As[ty * 4 + 0][k];
            const float a1 = As[ty * 4 + 1][k];
            const float a2 = As[ty * 4 + 2][k];
            const float a3 = As[ty * 4 + 3][k];
            const float4 b = *(const float4*)&Bs[k][tx << 2];
            acc[0][0] += a0 * b.x; acc[0][1] += a0 * b.y; acc[0][2] += a0 * b.z; acc[0][3] += a0 * b.w;
            acc[1][0] += a1 * b.x; acc[1][1] += a1 * b.y; acc[1][2] += a1 * b.z; acc[1][3] += a1 * b.w;
            acc[2][0] += a2 * b.x; acc[2][1] += a2 * b.y; acc[2][2] += a2 * b.z; acc[2][3] += a2 * b.w;
            acc[3][0] += a3 * b.x; acc[3][1] += a3 * b.y; acc[3][2] += a3 * b.z; acc[3][3] += a3 * b.w;
        }
        __syncthreads();
    }

    float* Cptr = FUSED ? C : (float*)g_Wh;
    #pragma unroll
    for (int i = 0; i < 4; i++) {
        const int row = bm + ty * 4 + i;
        if (row < M) {
            #pragma unroll
            for (int j = 0; j < 4; j++) {
                float v = acc[i][j];
                if (FUSED) v = (v > 0.f) ? v : expm1f(v);   // ELU(alpha=1)
                Cptr[(size_t)row * N + bn + (tx << 2) + j] = v;
            }
        }
    }
}

// ---------------- Wh1/Wh2 = Wh @ a[:F], Wh @ a[F:] ----------------
__global__ void wh12_kernel(const float* __restrict__ a_vec) {
    const int i   = blockIdx.x;
    const int tid = threadIdx.x;
    float s1 = 0.f, s2 = 0.f;
    for (int c = tid; c < OUT_F; c += 256) {
        const float w = g_Wh[(size_t)i * OUT_F + c];
        s1 += w * a_vec[c];
        s2 += w * a_vec[OUT_F + c];
    }
    __shared__ float r1[256], r2[256];
    r1[tid] = s1; r2[tid] = s2;
    __syncthreads();
    for (int s = 128; s > 0; s >>= 1) {
        if (tid < s) { r1[tid] += r1[tid + s]; r2[tid] += r2[tid + s]; }
        __syncthreads();
    }
    if (tid == 0) { g_Wh1[i] = r1[0]; g_Wh2[i] = r2[0]; }
}

// ---------------- per-row masked softmax for both adjacency masks ----------------
__global__ void attention_kernel(const int* __restrict__ adj1,
                                 const int* __restrict__ adj2) {
    const int i   = blockIdx.x;
    const int tid = threadIdx.x;
    __shared__ float l1s[N_NODES], l2s[N_NODES];
    __shared__ float red[256];

    const float wh1 = g_Wh1[i];
    float m1 = NEG_INF, m2 = NEG_INF;
    for (int j = tid; j < N_NODES; j += 256) {
        float e = wh1 + g_Wh2[j];
        e = (e > 0.f) ? e : ALPHA * e;           // LeakyReLU
        const float l1 = (adj1[(size_t)i * N_NODES + j] > 0) ? e : NEG_INF;
        const float l2 = (adj2[(size_t)i * N_NODES + j] > 0) ? e : NEG_INF;
        l1s[j] = l1; l2s[j] = l2;
        m1 = fmaxf(m1, l1); m2 = fmaxf(m2, l2);
    }
    // block max m1
    red[tid] = m1; __syncthreads();
    for (int s = 128; s > 0; s >>= 1) { if (tid < s) red[tid] = fmaxf(red[tid], red[tid + s]); __syncthreads(); }
    m1 = red[0]; __syncthreads();
    // block max m2
    red[tid] = m2; __syncthreads();
    for (int s = 128; s > 0; s >>= 1) { if (tid < s) red[tid] = fmaxf(red[tid], red[tid + s]); __syncthreads(); }
    m2 = red[0]; __syncthreads();

    float s1 = 0.f, s2 = 0.f;
    for (int j = tid; j < N_NODES; j += 256) {
        s1 += expf(l1s[j] - m1);
        s2 += expf(l2s[j] - m2);
    }
    red[tid] = s1; __syncthreads();
    for (int s = 128; s > 0; s >>= 1) { if (tid < s) red[tid] += red[tid + s]; __syncthreads(); }
    s1 = red[0]; __syncthreads();
    red[tid] = s2; __syncthreads();
    for (int s = 128; s > 0; s >>= 1) { if (tid < s) red[tid] += red[tid + s]; __syncthreads(); }
    s2 = red[0]; __syncthreads();

    const float inv1 = 1.f / s1;
    const float inv2 = 1.f / s2;
    for (int j = tid; j < N_NODES; j += 256) {
        g_att1[(size_t)i * N_NODES + j] = expf(l1s[j] - m1) * inv1;
        g_att2[(size_t)i * N_NODES + j] = expf(l2s[j] - m2) * inv2;
    }
}

// ---------------- 16x16 maxpool -> flatten -> linear (per map) ----------------
__global__ void pool_kernel(const float* __restrict__ L_w,
                            const float* __restrict__ L_b) {
    const int m = blockIdx.x;   // 0 or 1
    const float* att = (m == 0) ? g_att1 : g_att2;
    float acc = 0.f;
    for (int w = threadIdx.x; w < 54 * 54; w += blockDim.x) {
        const int wr = w / 54;
        const int wc = w - wr * 54;
        const float* base = att + (size_t)(wr * 16) * N_NODES + wc * 16;
        float mx = -INFINITY;
        #pragma unroll
        for (int r = 0; r < 16; r++) {
            #pragma unroll
            for (int c = 0; c < 16; c++)
                mx = fmaxf(mx, base[(size_t)r * N_NODES + c]);
        }
        acc += mx * L_w[w];
    }
    __shared__ float red[1024];
    red[threadIdx.x] = acc;
    __syncthreads();
    for (int s = 512; s > 0; s >>= 1) {
        if (threadIdx.x < s) red[threadIdx.x] += red[threadIdx.x + s];
        __syncthreads();
    }
    if (threadIdx.x == 0) g_logits[m] = red[0] + L_b[0];
}

// ---------------- leaky + softmax over the 2 fusion logits ----------------
__global__ void wgt_kernel() {
    float l0 = g_logits[0];
    float l1 = g_logits[1];
    l0 = (l0 > 0.f) ? l0 : ALPHA * l0;
    l1 = (l1 > 0.f) ? l1 : ALPHA * l1;
    const float mx = fmaxf(l0, l1);
    const float e0 = expf(l0 - mx);
    const float e1 = expf(l1 - mx);
    const float inv = 1.f / (e0 + e1);
    g_wgt[0] = e0 * inv;
    g_wgt[1] = e1 * inv;
}

// ---------------- launch ----------------
extern "C" void kernel_launch(void* const* d_in, const int* in_sizes, int n_in,
                              void* d_out, int out_size) {
    const float* h    = (const float*)d_in[0];
    // d_in[1] = adj (unused by the reference)
    const int*   adj1 = (const int*)d_in[2];
    const int*   adj2 = (const int*)d_in[3];
    const float* W    = (const float*)d_in[4];
    const float* a    = (const float*)d_in[5];
    const float* L_w  = (const float*)d_in[6];
    const float* L_b  = (const float*)d_in[7];
    float* out = (float*)d_out;

    const dim3 gemm_grid(OUT_F / 64, (N_NODES + 63) / 64);   // (16, 14)

    // 1. Wh = h @ W
    sgemm64_kernel<false><<<gemm_grid, 256>>>(h, W, nullptr, N_NODES, IN_F, OUT_F);
    // 2. Wh1/Wh2 row dots
    wh12_kernel<<<N_NODES, 256>>>(a);
    // 3. attention logits + masked softmaxes
    attention_kernel<<<N_NODES, 256>>>(adj1, adj2);
    // 4. pooled linear logits per map
    pool_kernel<<<2, 1024>>>(L_w, L_b);
    // 5. fusion weights
    wgt_kernel<<<1, 1>>>();
    // 6. out = elu( (w0*att1 + w1*att2) @ Wh )
    sgemm64_kernel<true><<<gemm_grid, 256>>>(nullptr, nullptr, out, N_NODES, N_NODES, OUT_F);
}

// round 3
// speedup vs baseline: 1.5715x; 1.5715x over previous
#include <cuda_runtime.h>
#include <math.h>

#define N_NODES 864
#define IN_F    4096
#define OUT_F   1024
#define ALPHA   0.2f
#define NEG_INF -9e15f
#define NPOOL   54            // 864/16
#define NWIN    (NPOOL*NPOOL) // 2916

// ---------------- device scratch (no allocation allowed) ----------------
__device__ float g_Wh[N_NODES * OUT_F];        // [864, 1024]
__device__ float g_att1[N_NODES * N_NODES];    // [864, 864]
__device__ float g_att2[N_NODES * N_NODES];    // [864, 864]
__device__ float g_Wh1[N_NODES];
__device__ float g_Wh2[N_NODES];
__device__ float g_pooled[2 * NWIN];
__device__ float g_logits[2];
__device__ float g_wgt[2];

// ---------------- f32x2 helpers (sm_103a packed fp32) ----------------
__device__ __forceinline__ unsigned long long pk2(float lo, float hi) {
    unsigned long long r;
    asm("mov.b64 %0, {%1, %2};" : "=l"(r) : "f"(lo), "f"(hi));
    return r;
}
#define FMA2(acc, a, b) \
    asm("fma.rn.f32x2 %0, %1, %2, %0;" : "+l"(acc) : "l"(a), "l"(b))

// ---------------- SGEMM: 128x64 tile, BK=16, 8x4 per thread, f32x2 ----------------
// FUSED=false: C(g_Wh) = A(h)[M,K] @ B(W)[K,N]
// FUSED=true : C(out)  = elu( (w0*att1 + w1*att2)[M,K] @ g_Wh[K,N] )
// A staged k-major (As[k][m]) so M-row pairs are contiguous 8B for LDS.64.
template <bool FUSED>
__global__ void sgemm128_kernel(const float* __restrict__ A,
                                const float* __restrict__ B,
                                float* __restrict__ C,
                                int M, int K, int N) {
    __shared__ float As[16][130];   // stride 130 ≡ 2 mod 32: conflict-free STS/LDS
    __shared__ float Bs[16][64];

    const int tid = threadIdx.x;    // 256 threads
    const int tx  = tid & 15;       // n: 0..15  (4 cols each)
    const int ty  = tid >> 4;       // m: 0..15  (8 rows each)
    const int bm  = blockIdx.y * 128;
    const int bn  = blockIdx.x * 64;

    // A-load mapping: two rows per thread, one float4 along k each
    const int arow = tid >> 2;          // 0..63 (and +64)
    const int acol = (tid & 3) << 2;    // 0,4,8,12
    // B-load mapping
    const int brow = tid >> 4;          // 0..15
    const int bcol = (tid & 15) << 2;   // 0..60

    float w0 = 0.f, w1 = 0.f;
    if (FUSED) { w0 = g_wgt[0]; w1 = g_wgt[1]; }
    const float* Bptr = FUSED ? (const float*)g_Wh : B;

    unsigned long long acc[4][4];       // [m-pair][n], each = (row even, row odd)
    #pragma unroll
    for (int p = 0; p < 4; p++)
        #pragma unroll
        for (int j = 0; j < 4; j++) acc[p][j] = 0ull;

    for (int k0 = 0; k0 < K; k0 += 16) {
        // stage A (transposed) — two rows per thread
        #pragma unroll
        for (int half = 0; half < 2; half++) {
            const int r    = arow + half * 64;
            const int grow = bm + r;
            float4 av = make_float4(0.f, 0.f, 0.f, 0.f);
            if (grow < M) {
                if (FUSED) {
                    const float4 a1 = *(const float4*)(g_att1 + (size_t)grow * N_NODES + k0 + acol);
                    const float4 a2 = *(const float4*)(g_att2 + (size_t)grow * N_NODES + k0 + acol);
                    av.x = w0 * a1.x + w1 * a2.x;
                    av.y = w0 * a1.y + w1 * a2.y;
                    av.z = w0 * a1.z + w1 * a2.z;
                    av.w = w0 * a1.w + w1 * a2.w;
                } else {
                    av = *(const float4*)(A + (size_t)grow * K + k0 + acol);
                }
            }
            As[acol + 0][r] = av.x;
            As[acol + 1][r] = av.y;
            As[acol + 2][r] = av.z;
            As[acol + 3][r] = av.w;
        }
        // stage B
        *(float4*)&Bs[brow][bcol] =
            *(const float4*)(Bptr + (size_t)(k0 + brow) * N + bn + bcol);

        __syncthreads();

        #pragma unroll
        for (int k = 0; k < 16; k++) {
            const int mbase = ty << 3;
            const unsigned long long a0 = *(const unsigned long long*)&As[k][mbase + 0];
            const unsigned long long a1 = *(const unsigned long long*)&As[k][mbase + 2];
            const unsigned long long a2 = *(const unsigned long long*)&As[k][mbase + 4];
            const unsigned long long a3 = *(const unsigned long long*)&As[k][mbase + 6];
            const float4 b = *(const float4*)&Bs[k][tx << 2];
            const unsigned long long b0 = pk2(b.x, b.x);
            const unsigned long long b1 = pk2(b.y, b.y);
            const unsigned long long b2 = pk2(b.z, b.z);
            const unsigned long long b3 = pk2(b.w, b.w);
            FMA2(acc[0][0], a0, b0); FMA2(acc[0][1], a0, b1); FMA2(acc[0][2], a0, b2); FMA2(acc[0][3], a0, b3);
            FMA2(acc[1][0], a1, b0); FMA2(acc[1][1], a1, b1); FMA2(acc[1][2], a1, b2); FMA2(acc[1][3], a1, b3);
            FMA2(acc[2][0], a2, b0); FMA2(acc[2][1], a2, b1); FMA2(acc[2][2], a2, b2); FMA2(acc[2][3], a2, b3);
            FMA2(acc[3][0], a3, b0); FMA2(acc[3][1], a3, b1); FMA2(acc[3][2], a3, b2); FMA2(acc[3][3], a3, b3);
        }
        __syncthreads();
    }

    float* Cptr = FUSED ? C : (float*)g_Wh;
    #pragma unroll
    for (int p = 0; p < 4; p++) {
        const int row0 = bm + (ty << 3) + (p << 1);
        float4 lo, hi;
        float2 v0 = *(float2*)&acc[p][0];
        float2 v1 = *(float2*)&acc[p][1];
        float2 v2 = *(float2*)&acc[p][2];
        float2 v3 = *(float2*)&acc[p][3];
        lo = make_float4(v0.x, v1.x, v2.x, v3.x);
        hi = make_float4(v0.y, v1.y, v2.y, v3.y);
        if (FUSED) {
            lo.x = lo.x > 0.f ? lo.x : expm1f(lo.x);
            lo.y = lo.y > 0.f ? lo.y : expm1f(lo.y);
            lo.z = lo.z > 0.f ? lo.z : expm1f(lo.z);
            lo.w = lo.w > 0.f ? lo.w : expm1f(lo.w);
            hi.x = hi.x > 0.f ? hi.x : expm1f(hi.x);
            hi.y = hi.y > 0.f ? hi.y : expm1f(hi.y);
            hi.z = hi.z > 0.f ? hi.z : expm1f(hi.z);
            hi.w = hi.w > 0.f ? hi.w : expm1f(hi.w);
        }
        if (row0 < M)
            *(float4*)(Cptr + (size_t)row0 * N + bn + (tx << 2)) = lo;
        if (row0 + 1 < M)
            *(float4*)(Cptr + (size_t)(row0 + 1) * N + bn + (tx << 2)) = hi;
    }
}

// ---------------- Wh1/Wh2 = Wh @ a[:F], Wh @ a[F:] ----------------
__global__ void wh12_kernel(const float* __restrict__ a_vec) {
    const int i   = blockIdx.x;
    const int tid = threadIdx.x;
    float s1 = 0.f, s2 = 0.f;
    for (int c = tid; c < OUT_F; c += 256) {
        const float w = g_Wh[(size_t)i * OUT_F + c];
        s1 += w * a_vec[c];
        s2 += w * a_vec[OUT_F + c];
    }
    __shared__ float r1[256], r2[256];
    r1[tid] = s1; r2[tid] = s2;
    __syncthreads();
    for (int s = 128; s > 0; s >>= 1) {
        if (tid < s) { r1[tid] += r1[tid + s]; r2[tid] += r2[tid + s]; }
        __syncthreads();
    }
    if (tid == 0) { g_Wh1[i] = r1[0]; g_Wh2[i] = r2[0]; }
}

// ---------------- per-row masked softmax for both adjacency masks ----------------
__global__ void attention_kernel(const int* __restrict__ adj1,
                                 const int* __restrict__ adj2) {
    const int i   = blockIdx.x;
    const int tid = threadIdx.x;
    __shared__ float l1s[N_NODES], l2s[N_NODES];
    __shared__ float red[256];

    const float wh1 = g_Wh1[i];
    float m1 = NEG_INF, m2 = NEG_INF;
    for (int j = tid; j < N_NODES; j += 256) {
        float e = wh1 + g_Wh2[j];
        e = (e > 0.f) ? e : ALPHA * e;           // LeakyReLU
        const float l1 = (adj1[(size_t)i * N_NODES + j] > 0) ? e : NEG_INF;
        const float l2 = (adj2[(size_t)i * N_NODES + j] > 0) ? e : NEG_INF;
        l1s[j] = l1; l2s[j] = l2;
        m1 = fmaxf(m1, l1); m2 = fmaxf(m2, l2);
    }
    red[tid] = m1; __syncthreads();
    for (int s = 128; s > 0; s >>= 1) { if (tid < s) red[tid] = fmaxf(red[tid], red[tid + s]); __syncthreads(); }
    m1 = red[0]; __syncthreads();
    red[tid] = m2; __syncthreads();
    for (int s = 128; s > 0; s >>= 1) { if (tid < s) red[tid] = fmaxf(red[tid], red[tid + s]); __syncthreads(); }
    m2 = red[0]; __syncthreads();

    float s1 = 0.f, s2 = 0.f;
    for (int j = tid; j < N_NODES; j += 256) {
        s1 += expf(l1s[j] - m1);
        s2 += expf(l2s[j] - m2);
    }
    red[tid] = s1; __syncthreads();
    for (int s = 128; s > 0; s >>= 1) { if (tid < s) red[tid] += red[tid + s]; __syncthreads(); }
    s1 = red[0]; __syncthreads();
    red[tid] = s2; __syncthreads();
    for (int s = 128; s > 0; s >>= 1) { if (tid < s) red[tid] += red[tid + s]; __syncthreads(); }
    s2 = red[0]; __syncthreads();

    const float inv1 = 1.f / s1;
    const float inv2 = 1.f / s2;
    for (int j = tid; j < N_NODES; j += 256) {
        g_att1[(size_t)i * N_NODES + j] = expf(l1s[j] - m1) * inv1;
        g_att2[(size_t)i * N_NODES + j] = expf(l2s[j] - m2) * inv2;
    }
}

// ---------------- 16x16 maxpool: one WARP per window ----------------
__global__ void pool_max_kernel() {
    const int warp = (blockIdx.x << 3) + (threadIdx.x >> 5);   // global warp id
    if (warp >= 2 * NWIN) return;
    const int lane = threadIdx.x & 31;

    const int m  = warp / NWIN;
    const int w  = warp - m * NWIN;
    const int wr = w / NPOOL;
    const int wc = w - wr * NPOOL;

    const float* __restrict__ att = (m == 0) ? g_att1 : g_att2;
    const float* base = att + (size_t)(wr * 16) * N_NODES + wc * 16;

    float mx = -INFINITY;
    #pragma unroll
    for (int it = 0; it < 8; it++) {
        const int idx = lane + (it << 5);   // 0..255
        const int r = idx >> 4;
        const int c = idx & 15;
        mx = fmaxf(mx, base[(size_t)r * N_NODES + c]);
    }
    #pragma unroll
    for (int s = 16; s > 0; s >>= 1)
        mx = fmaxf(mx, __shfl_xor_sync(0xffffffffu, mx, s));
    if (lane == 0) g_pooled[warp] = mx;
}

// ---------------- logits[m] = pooled[m] . L_w + L_b ----------------
__global__ void logits_kernel(const float* __restrict__ L_w,
                              const float* __restrict__ L_b) {
    const int m   = blockIdx.x;   // 0 or 1
    const int tid = threadIdx.x;  // 1024 threads
    float acc = 0.f;
    for (int i = tid; i < NWIN; i += 1024)
        acc += g_pooled[m * NWIN + i] * L_w[i];
    __shared__ float red[1024];
    red[tid] = acc;
    __syncthreads();
    for (int s = 512; s > 0; s >>= 1) {
        if (tid < s) red[tid] += red[tid + s];
        __syncthreads();
    }
    if (tid == 0) g_logits[m] = red[0] + L_b[0];
}

// ---------------- leaky + softmax over the 2 fusion logits ----------------
__global__ void wgt_kernel() {
    float l0 = g_logits[0];
    float l1 = g_logits[1];
    l0 = (l0 > 0.f) ? l0 : ALPHA * l0;
    l1 = (l1 > 0.f) ? l1 : ALPHA * l1;
    const float mx = fmaxf(l0, l1);
    const float e0 = expf(l0 - mx);
    const float e1 = expf(l1 - mx);
    const float inv = 1.f / (e0 + e1);
    g_wgt[0] = e0 * inv;
    g_wgt[1] = e1 * inv;
}

// ---------------- launch ----------------
extern "C" void kernel_launch(void* const* d_in, const int* in_sizes, int n_in,
                              void* d_out, int out_size) {
    const float* h    = (const float*)d_in[0];
    // d_in[1] = adj (unused by the reference)
    const int*   adj1 = (const int*)d_in[2];
    const int*   adj2 = (const int*)d_in[3];
    const float* W    = (const float*)d_in[4];
    const float* a    = (const float*)d_in[5];
    const float* L_w  = (const float*)d_in[6];
    const float* L_b  = (const float*)d_in[7];
    float* out = (float*)d_out;

    const dim3 gemm_grid(OUT_F / 64, (N_NODES + 127) / 128);   // (16, 7)

    // 1. Wh = h @ W
    sgemm128_kernel<false><<<gemm_grid, 256>>>(h, W, nullptr, N_NODES, IN_F, OUT_F);
    // 2. Wh1/Wh2 row dots
    wh12_kernel<<<N_NODES, 256>>>(a);
    // 3. attention logits + masked softmaxes
    attention_kernel<<<N_NODES, 256>>>(adj1, adj2);
    // 4. 16x16 maxpool (one warp per window)
    pool_max_kernel<<<(2 * NWIN + 7) / 8, 256>>>();
    // 5. pooled . L_w + b per map
    logits_kernel<<<2, 1024>>>(L_w, L_b);
    // 6. fusion weights
    wgt_kernel<<<1, 1>>>();
    // 7. out = elu( (w0*att1 + w1*att2) @ Wh )
    sgemm128_kernel<true><<<gemm_grid, 256>>>(nullptr, nullptr, out, N_NODES, N_NODES, OUT_F);
}

// round 11
// speedup vs baseline: 2.6577x; 1.6912x over previous
#include <cuda_runtime.h>
#include <cuda_bf16.h>
#include <stdint.h>
#include <math.h>

#define N_NODES 864
#define IN_F    4096
#define OUT_F   1024
#define ALPHA   0.2f
#define NEG_INF -9e15f
#define NPOOL   54
#define NWIN    (NPOOL*NPOOL)

// ---------------- device scratch (no allocation allowed) ----------------
__device__ float g_Wh[N_NODES * OUT_F];
__device__ float g_att1[N_NODES * N_NODES];
__device__ float g_att2[N_NODES * N_NODES];
__device__ float g_Wh1[N_NODES];
__device__ float g_Wh2[N_NODES];
__device__ float g_pooled[2 * NWIN];
__device__ float g_logits[2];
__device__ float g_wgt[2];
// bf16 split operands for GEMM1
__device__ __nv_bfloat16 g_Ahi[N_NODES * IN_F];   // h hi [m][k]
__device__ __nv_bfloat16 g_Alo[N_NODES * IN_F];   // h lo
__device__ __nv_bfloat16 g_Bhi[OUT_F * IN_F];     // W^T hi [n][k]
__device__ __nv_bfloat16 g_Blo[OUT_F * IN_F];     // W^T lo

// ---------------- helpers ----------------
__device__ __forceinline__ uint32_t smem_u32(const void* p) {
    uint32_t a;
    asm("{ .reg .u64 t; cvta.to.shared.u64 t, %1; cvt.u32.u64 %0, t; }" : "=r"(a) : "l"(p));
    return a;
}
// swizzle 16B chunks within a 128B row: off ^ ((row&7)<<4)
#define SW128(o) ((o) ^ (((o) >> 3) & 0x70))

__device__ __forceinline__ void ldsm_x4(uint32_t* r, uint32_t addr) {
    asm volatile("ldmatrix.sync.aligned.m8n8.x4.shared.b16 {%0,%1,%2,%3}, [%4];"
        : "=r"(r[0]), "=r"(r[1]), "=r"(r[2]), "=r"(r[3]) : "r"(addr));
}
__device__ __forceinline__ void mma_bf16(float* d, const uint32_t* a, uint32_t b0, uint32_t b1) {
    asm volatile("mma.sync.aligned.m16n8k16.row.col.f32.bf16.bf16.f32 "
        "{%0,%1,%2,%3}, {%4,%5,%6,%7}, {%8,%9}, {%0,%1,%2,%3};"
        : "+f"(d[0]), "+f"(d[1]), "+f"(d[2]), "+f"(d[3])
        : "r"(a[0]), "r"(a[1]), "r"(a[2]), "r"(a[3]), "r"(b0), "r"(b1));
}

// ---------------- conversion kernels ----------------
__global__ void convert_h_kernel(const float* __restrict__ h) {
    const int i = blockIdx.x * blockDim.x + threadIdx.x;     // float4 idx
    if (i >= N_NODES * IN_F / 4) return;
    const float4 v = ((const float4*)h)[i];
    __nv_bfloat162 h01 = __floats2bfloat162_rn(v.x, v.y);
    __nv_bfloat162 h23 = __floats2bfloat162_rn(v.z, v.w);
    float2 f01 = __bfloat1622float2(h01);
    float2 f23 = __bfloat1622float2(h23);
    __nv_bfloat162 l01 = __floats2bfloat162_rn(v.x - f01.x, v.y - f01.y);
    __nv_bfloat162 l23 = __floats2bfloat162_rn(v.z - f23.x, v.w - f23.y);
    ((__nv_bfloat162*)g_Ahi)[2 * i]     = h01;
    ((__nv_bfloat162*)g_Ahi)[2 * i + 1] = h23;
    ((__nv_bfloat162*)g_Alo)[2 * i]     = l01;
    ((__nv_bfloat162*)g_Alo)[2 * i + 1] = l23;
}

// W [4096,1024] -> W^T hi/lo [1024,4096] via 32x32 smem tile transpose
__global__ void convert_w_kernel(const float* __restrict__ W) {
    __shared__ float t[32][33];
    const int n0 = blockIdx.x * 32;
    const int k0 = blockIdx.y * 32;
    const int tx = threadIdx.x, ty = threadIdx.y;   // 32 x 8
    #pragma unroll
    for (int i = 0; i < 32; i += 8)
        t[ty + i][tx] = W[(size_t)(k0 + ty + i) * OUT_F + n0 + tx];
    __syncthreads();
    #pragma unroll
    for (int i = 0; i < 32; i += 8) {
        const float v = t[tx][ty + i];               // W[k0+tx][n0+ty+i]
        const __nv_bfloat16 hi = __float2bfloat16(v);
        const float lo = v - __bfloat162float(hi);
        const size_t o = (size_t)(n0 + ty + i) * IN_F + k0 + tx;
        g_Bhi[o] = hi;
        g_Blo[o] = __float2bfloat16(lo);
    }
}

// ---------------- GEMM1 via mma.sync (HMMA, bf16 3-term split) ----------------
// CTA tile 128x64, 8 warps (4m x 2n), warp tile 32x32, K-chunk 64.
// smem layout (rows of 128B, SW128-swizzled 16B chunks):
//   [0)       A hi 128x64 bf16  (16 KB)
//   [16384)   A lo              (16 KB)
//   [32768)   B hi  64x64 bf16  ( 8 KB)
//   [40960)   B lo              ( 8 KB)
__global__ void __launch_bounds__(256, 1) gemm1_mma_kernel() {
    __shared__ __align__(1024) char smem[49152];
    const uint32_t sb = smem_u32(smem);
    const int tid  = threadIdx.x;
    const int lane = tid & 31;
    const int warp = tid >> 5;
    const int wm   = warp & 3;       // 0..3  (m quadrant, 32 rows)
    const int wn   = warp >> 2;      // 0..1  (n half, 32 cols)
    const int bm = blockIdx.y * 128;
    const int bn = blockIdx.x * 64;
    const int mvalid = (N_NODES - bm < 128) ? (N_NODES - bm) : 128;

    float acc[2][4][4];              // [mi(16)][n8][4]
    #pragma unroll
    for (int mi = 0; mi < 2; mi++)
        #pragma unroll
        for (int nj = 0; nj < 4; nj++)
            #pragma unroll
            for (int q = 0; q < 4; q++) acc[mi][nj][q] = 0.f;

    // ldmatrix per-lane address components (within a 16x16 tile; byte units)
    const int a_r = ((lane >> 3) & 1) * 8 + (lane & 7);   // row in tile
    const int a_c = (lane >> 4) * 16;                     // 0 or 16 bytes
    const int b_r = ((lane >> 4) & 1) * 8 + (lane & 7);
    const int b_c = ((lane >> 3) & 1) * 16;

    const int NCH = IN_F / 64;       // 64 chunks

    for (int c = 0; c < NCH; c++) {
        const int k0 = c * 64;
        // ---- stage chunk: A hi/lo (128 rows x 128B), B hi/lo (64 rows x 128B)
        #pragma unroll
        for (int it = 0; it < 4; it++) {
            const int s = tid + it * 256;        // 0..1023
            const int r = s >> 3, cc = s & 7;
            const uint32_t off = SW128((uint32_t)(r * 128 + cc * 16));
            uint4 vh = make_uint4(0, 0, 0, 0), vl = vh;
            if (r < mvalid) {
                const size_t gi = (size_t)(bm + r) * IN_F + k0 + cc * 8;
                vh = *(const uint4*)(g_Ahi + gi);
                vl = *(const uint4*)(g_Alo + gi);
            }
            *(uint4*)(smem + off)         = vh;
            *(uint4*)(smem + 16384 + off) = vl;
        }
        #pragma unroll
        for (int it = 0; it < 2; it++) {
            const int s = tid + it * 256;        // 0..511
            const int r = s >> 3, cc = s & 7;
            const uint32_t off = SW128((uint32_t)(r * 128 + cc * 16));
            const size_t gi = (size_t)(bn + r) * IN_F + k0 + cc * 8;
            *(uint4*)(smem + 32768 + off) = *(const uint4*)(g_Bhi + gi);
            *(uint4*)(smem + 40960 + off) = *(const uint4*)(g_Blo + gi);
        }
        __syncthreads();

        // ---- 4 k16 steps
        #pragma unroll
        for (int s = 0; s < 4; s++) {
            const int kb = s * 32;               // byte offset of k16 within row
            uint32_t ah[2][4], al[2][4];
            #pragma unroll
            for (int mi = 0; mi < 2; mi++) {
                const int row = wm * 32 + mi * 16 + a_r;
                const uint32_t co = (uint32_t)(kb + a_c) ^ (uint32_t)((row & 7) << 4);
                ldsm_x4(ah[mi], sb + row * 128 + co);
                ldsm_x4(al[mi], sb + 16384 + row * 128 + co);
            }
            uint32_t bh[2][4], bl[2][4];         // [n16 group][4]: r0,r1=n8#0 frag, r2,r3=n8#1
            #pragma unroll
            for (int nj = 0; nj < 2; nj++) {
                const int row = wn * 32 + nj * 16 + b_r;
                const uint32_t co = (uint32_t)(kb + b_c) ^ (uint32_t)((row & 7) << 4);
                ldsm_x4(bh[nj], sb + 32768 + row * 128 + co);
                ldsm_x4(bl[nj], sb + 40960 + row * 128 + co);
            }
            #pragma unroll
            for (int mi = 0; mi < 2; mi++) {
                #pragma unroll
                for (int n8 = 0; n8 < 4; n8++) {
                    const int g = n8 >> 1, h = (n8 & 1) * 2;
                    mma_bf16(acc[mi][n8], ah[mi], bh[g][h], bh[g][h + 1]);   // hi*hi
                    mma_bf16(acc[mi][n8], ah[mi], bl[g][h], bl[g][h + 1]);   // hi*lo
                    mma_bf16(acc[mi][n8], al[mi], bh[g][h], bh[g][h + 1]);   // lo*hi
                }
            }
        }
        __syncthreads();
    }

    // ---- epilogue: store to g_Wh
    #pragma unroll
    for (int mi = 0; mi < 2; mi++) {
        #pragma unroll
        for (int n8 = 0; n8 < 4; n8++) {
            const int row0 = bm + wm * 32 + mi * 16 + (lane >> 2);
            const int col  = bn + wn * 32 + n8 * 8 + (lane & 3) * 2;
            if (row0 < N_NODES)
                *(float2*)(g_Wh + (size_t)row0 * OUT_F + col) =
                    make_float2(acc[mi][n8][0], acc[mi][n8][1]);
            if (row0 + 8 < N_NODES)
                *(float2*)(g_Wh + (size_t)(row0 + 8) * OUT_F + col) =
                    make_float2(acc[mi][n8][2], acc[mi][n8][3]);
        }
    }
}

// ---------------- f32x2 fused GEMM2 (proven path) ----------------
__device__ __forceinline__ unsigned long long pk2(float lo, float hi) {
    unsigned long long r;
    asm("mov.b64 %0, {%1, %2};" : "=l"(r) : "f"(lo), "f"(hi));
    return r;
}
#define FMA2(acc, a, b) \
    asm("fma.rn.f32x2 %0, %1, %2, %0;" : "+l"(acc) : "l"(a), "l"(b))

__global__ void sgemm_fused_kernel(float* __restrict__ C) {
    __shared__ float As[16][130];
    __shared__ float Bs[16][64];
    const int tid = threadIdx.x;
    const int tx  = tid & 15;
    const int ty  = tid >> 4;
    const int bm  = blockIdx.y * 128;
    const int bn  = blockIdx.x * 64;
    const int arow = tid >> 2;
    const int acol = (tid & 3) << 2;
    const int brow = tid >> 4;
    const int bcol = (tid & 15) << 2;
    const float w0 = g_wgt[0], w1 = g_wgt[1];
    const int M = N_NODES, K = N_NODES, N = OUT_F;

    unsigned long long acc[4][4];
    #pragma unroll
    for (int p = 0; p < 4; p++)
        #pragma unroll
        for (int j = 0; j < 4; j++) acc[p][j] = 0ull;

    for (int k0 = 0; k0 < K; k0 += 16) {
        #pragma unroll
        for (int half = 0; half < 2; half++) {
            const int r    = arow + half * 64;
            const int grow = bm + r;
            float4 av = make_float4(0.f, 0.f, 0.f, 0.f);
            if (grow < M) {
                const float4 a1 = *(const float4*)(g_att1 + (size_t)grow * N_NODES + k0 + acol);
                const float4 a2 = *(const float4*)(g_att2 + (size_t)grow * N_NODES + k0 + acol);
                av.x = w0 * a1.x + w1 * a2.x;
                av.y = w0 * a1.y + w1 * a2.y;
                av.z = w0 * a1.z + w1 * a2.z;
                av.w = w0 * a1.w + w1 * a2.w;
            }
            As[acol + 0][r] = av.x;
            As[acol + 1][r] = av.y;
            As[acol + 2][r] = av.z;
            As[acol + 3][r] = av.w;
        }
        *(float4*)&Bs[brow][bcol] =
            *(const float4*)(g_Wh + (size_t)(k0 + brow) * N + bn + bcol);
        __syncthreads();
        #pragma unroll
        for (int k = 0; k < 16; k++) {
            const int mbase = ty << 3;
            const unsigned long long a0 = *(const unsigned long long*)&As[k][mbase + 0];
            const unsigned long long a1 = *(const unsigned long long*)&As[k][mbase + 2];
            const unsigned long long a2 = *(const unsigned long long*)&As[k][mbase + 4];
            const unsigned long long a3 = *(const unsigned long long*)&As[k][mbase + 6];
            const float4 b = *(const float4*)&Bs[k][tx << 2];
            const unsigned long long b0 = pk2(b.x, b.x);
            const unsigned long long b1 = pk2(b.y, b.y);
            const unsigned long long b2 = pk2(b.z, b.z);
            const unsigned long long b3 = pk2(b.w, b.w);
            FMA2(acc[0][0], a0, b0); FMA2(acc[0][1], a0, b1); FMA2(acc[0][2], a0, b2); FMA2(acc[0][3], a0, b3);
            FMA2(acc[1][0], a1, b0); FMA2(acc[1][1], a1, b1); FMA2(acc[1][2], a1, b2); FMA2(acc[1][3], a1, b3);
            FMA2(acc[2][0], a2, b0); FMA2(acc[2][1], a2, b1); FMA2(acc[2][2], a2, b2); FMA2(acc[2][3], a2, b3);
            FMA2(acc[3][0], a3, b0); FMA2(acc[3][1], a3, b1); FMA2(acc[3][2], a3, b2); FMA2(acc[3][3], a3, b3);
        }
        __syncthreads();
    }
    #pragma unroll
    for (int p = 0; p < 4; p++) {
        const int row0 = bm + (ty << 3) + (p << 1);
        float2 v0 = *(float2*)&acc[p][0];
        float2 v1 = *(float2*)&acc[p][1];
        float2 v2 = *(float2*)&acc[p][2];
        float2 v3 = *(float2*)&acc[p][3];
        float4 lo = make_float4(v0.x, v1.x, v2.x, v3.x);
        float4 hi = make_float4(v0.y, v1.y, v2.y, v3.y);
        lo.x = lo.x > 0.f ? lo.x : expm1f(lo.x);
        lo.y = lo.y > 0.f ? lo.y : expm1f(lo.y);
        lo.z = lo.z > 0.f ? lo.z : expm1f(lo.z);
        lo.w = lo.w > 0.f ? lo.w : expm1f(lo.w);
        hi.x = hi.x > 0.f ? hi.x : expm1f(hi.x);
        hi.y = hi.y > 0.f ? hi.y : expm1f(hi.y);
        hi.z = hi.z > 0.f ? hi.z : expm1f(hi.z);
        hi.w = hi.w > 0.f ? hi.w : expm1f(hi.w);
        if (row0 < M)     *(float4*)(C + (size_t)row0 * N + bn + (tx << 2)) = lo;
        if (row0 + 1 < M) *(float4*)(C + (size_t)(row0 + 1) * N + bn + (tx << 2)) = hi;
    }
}

// ---------------- small kernels ----------------
__global__ void wh12_kernel(const float* __restrict__ a_vec) {
    const int i   = blockIdx.x;
    const int tid = threadIdx.x;
    float s1 = 0.f, s2 = 0.f;
    for (int c = tid; c < OUT_F; c += 256) {
        const float w = g_Wh[(size_t)i * OUT_F + c];
        s1 += w * a_vec[c];
        s2 += w * a_vec[OUT_F + c];
    }
    __shared__ float r1[256], r2[256];
    r1[tid] = s1; r2[tid] = s2;
    __syncthreads();
    for (int s = 128; s > 0; s >>= 1) {
        if (tid < s) { r1[tid] += r1[tid + s]; r2[tid] += r2[tid + s]; }
        __syncthreads();
    }
    if (tid == 0) { g_Wh1[i] = r1[0]; g_Wh2[i] = r2[0]; }
}

__global__ void attention_kernel(const int* __restrict__ adj1,
                                 const int* __restrict__ adj2) {
    const int i   = blockIdx.x;
    const int tid = threadIdx.x;
    __shared__ float l1s[N_NODES], l2s[N_NODES];
    __shared__ float red[256];
    const float wh1 = g_Wh1[i];
    float m1 = NEG_INF, m2 = NEG_INF;
    for (int j = tid; j < N_NODES; j += 256) {
        float e = wh1 + g_Wh2[j];
        e = (e > 0.f) ? e : ALPHA * e;
        const float l1 = (adj1[(size_t)i * N_NODES + j] > 0) ? e : NEG_INF;
        const float l2 = (adj2[(size_t)i * N_NODES + j] > 0) ? e : NEG_INF;
        l1s[j] = l1; l2s[j] = l2;
        m1 = fmaxf(m1, l1); m2 = fmaxf(m2, l2);
    }
    red[tid] = m1; __syncthreads();
    for (int s = 128; s > 0; s >>= 1) { if (tid < s) red[tid] = fmaxf(red[tid], red[tid + s]); __syncthreads(); }
    m1 = red[0]; __syncthreads();
    red[tid] = m2; __syncthreads();
    for (int s = 128; s > 0; s >>= 1) { if (tid < s) red[tid] = fmaxf(red[tid], red[tid + s]); __syncthreads(); }
    m2 = red[0]; __syncthreads();
    float s1 = 0.f, s2 = 0.f;
    for (int j = tid; j < N_NODES; j += 256) {
        s1 += expf(l1s[j] - m1);
        s2 += expf(l2s[j] - m2);
    }
    red[tid] = s1; __syncthreads();
    for (int s = 128; s > 0; s >>= 1) { if (tid < s) red[tid] += red[tid + s]; __syncthreads(); }
    s1 = red[0]; __syncthreads();
    red[tid] = s2; __syncthreads();
    for (int s = 128; s > 0; s >>= 1) { if (tid < s) red[tid] += red[tid + s]; __syncthreads(); }
    s2 = red[0]; __syncthreads();
    const float inv1 = 1.f / s1;
    const float inv2 = 1.f / s2;
    for (int j = tid; j < N_NODES; j += 256) {
        g_att1[(size_t)i * N_NODES + j] = expf(l1s[j] - m1) * inv1;
        g_att2[(size_t)i * N_NODES + j] = expf(l2s[j] - m2) * inv2;
    }
}

__global__ void pool_max_kernel() {
    const int warp = (blockIdx.x << 3) + (threadIdx.x >> 5);
    if (warp >= 2 * NWIN) return;
    const int lane = threadIdx.x & 31;
    const int m  = warp / NWIN;
    const int w  = warp - m * NWIN;
    const int wr = w / NPOOL;
    const int wc = w - wr * NPOOL;
    const float* __restrict__ att = (m == 0) ? g_att1 : g_att2;
    const float* base = att + (size_t)(wr * 16) * N_NODES + wc * 16;
    float mx = -INFINITY;
    #pragma unroll
    for (int it = 0; it < 8; it++) {
        const int idx = lane + (it << 5);
        const int r = idx >> 4;
        const int c = idx & 15;
        mx = fmaxf(mx, base[(size_t)r * N_NODES + c]);
    }
    #pragma unroll
    for (int s = 16; s > 0; s >>= 1)
        mx = fmaxf(mx, __shfl_xor_sync(0xffffffffu, mx, s));
    if (lane == 0) g_pooled[warp] = mx;
}

__global__ void logits_kernel(const float* __restrict__ L_w,
                              const float* __restrict__ L_b) {
    const int m   = blockIdx.x;
    const int tid = threadIdx.x;
    float acc = 0.f;
    for (int i = tid; i < NWIN; i += 1024)
        acc += g_pooled[m * NWIN + i] * L_w[i];
    __shared__ float red[1024];
    red[tid] = acc;
    __syncthreads();
    for (int s = 512; s > 0; s >>= 1) {
        if (tid < s) red[tid] += red[tid + s];
        __syncthreads();
    }
    if (tid == 0) g_logits[m] = red[0] + L_b[0];
}

__global__ void wgt_kernel() {
    float l0 = g_logits[0];
    float l1 = g_logits[1];
    l0 = (l0 > 0.f) ? l0 : ALPHA * l0;
    l1 = (l1 > 0.f) ? l1 : ALPHA * l1;
    const float mx = fmaxf(l0, l1);
    const float e0 = expf(l0 - mx);
    const float e1 = expf(l1 - mx);
    const float inv = 1.f / (e0 + e1);
    g_wgt[0] = e0 * inv;
    g_wgt[1] = e1 * inv;
}

// ---------------- launch ----------------
extern "C" void kernel_launch(void* const* d_in, const int* in_sizes, int n_in,
                              void* d_out, int out_size) {
    const float* h    = (const float*)d_in[0];
    const int*   adj1 = (const int*)d_in[2];
    const int*   adj2 = (const int*)d_in[3];
    const float* W    = (const float*)d_in[4];
    const float* a    = (const float*)d_in[5];
    const float* L_w  = (const float*)d_in[6];
    const float* L_b  = (const float*)d_in[7];
    float* out = (float*)d_out;

    // 0. split conversions
    convert_h_kernel<<<(N_NODES * IN_F / 4 + 255) / 256, 256>>>(h);
    convert_w_kernel<<<dim3(OUT_F / 32, IN_F / 32), dim3(32, 8)>>>(W);
    // 1. Wh = h @ W  (mma.sync bf16 3-term split)
    gemm1_mma_kernel<<<dim3(OUT_F / 64, (N_NODES + 127) / 128), 256>>>();
    // 2. Wh1/Wh2 row dots
    wh12_kernel<<<N_NODES, 256>>>(a);
    // 3. attention logits + masked softmaxes
    attention_kernel<<<N_NODES, 256>>>(adj1, adj2);
    // 4. 16x16 maxpool
    pool_max_kernel<<<(2 * NWIN + 7) / 8, 256>>>();
    // 5. pooled . L_w + b per map
    logits_kernel<<<2, 1024>>>(L_w, L_b);
    // 6. fusion weights
    wgt_kernel<<<1, 1>>>();
    // 7. out = elu( (w0*att1 + w1*att2) @ Wh )
    sgemm_fused_kernel<<<dim3(OUT_F / 64, (N_NODES + 127) / 128), 256>>>(out);
}

// round 16
// speedup vs baseline: 4.2685x; 1.6061x over previous
#include <cuda_runtime.h>
#include <cuda_bf16.h>
#include <stdint.h>
#include <math.h>

#define N_NODES 864
#define IN_F    4096
#define OUT_F   1024
#define K2PAD   896            // 864 padded to 14*64
#define ALPHA   0.2f
#define NEG_INF -9e15f
#define NPOOL   54
#define NWIN    (NPOOL*NPOOL)

// ---------------- device scratch (no allocation allowed) ----------------
__device__ float g_Wh[N_NODES * OUT_F];
__device__ float g_att1[N_NODES * N_NODES];
__device__ float g_att2[N_NODES * N_NODES];
__device__ float g_Wh1[N_NODES];
__device__ float g_Wh2[N_NODES];
__device__ float g_pooled[2 * NWIN];
__device__ float g_logits[2];
__device__ float g_wgt[2];
// GEMM1 operands (bf16 split)
__device__ __nv_bfloat16 g_Ahi[N_NODES * IN_F];
__device__ __nv_bfloat16 g_Alo[N_NODES * IN_F];
__device__ __nv_bfloat16 g_Bhi[OUT_F * IN_F];     // W^T [n][k]
__device__ __nv_bfloat16 g_Blo[OUT_F * IN_F];
// GEMM2 operands (bf16 split, K padded to 896)
__device__ __nv_bfloat16 g_A2hi[N_NODES * K2PAD];   // fused att [m][k]
__device__ __nv_bfloat16 g_A2lo[N_NODES * K2PAD];
__device__ __nv_bfloat16 g_WThi[OUT_F * K2PAD];     // Wh^T [n][k]
__device__ __nv_bfloat16 g_WTlo[OUT_F * K2PAD];

// ---------------- helpers ----------------
__device__ __forceinline__ uint32_t smem_u32(const void* p) {
    uint32_t a;
    asm("{ .reg .u64 t; cvta.to.shared.u64 t, %1; cvt.u32.u64 %0, t; }" : "=r"(a) : "l"(p));
    return a;
}
#define SW128(o) ((o) ^ (((o) >> 3) & 0x70))

__device__ __forceinline__ void ldsm_x4(uint32_t* r, uint32_t addr) {
    asm volatile("ldmatrix.sync.aligned.m8n8.x4.shared.b16 {%0,%1,%2,%3}, [%4];"
        : "=r"(r[0]), "=r"(r[1]), "=r"(r[2]), "=r"(r[3]) : "r"(addr));
}
__device__ __forceinline__ void mma_bf16(float* d, const uint32_t* a, uint32_t b0, uint32_t b1) {
    asm volatile("mma.sync.aligned.m16n8k16.row.col.f32.bf16.bf16.f32 "
        "{%0,%1,%2,%3}, {%4,%5,%6,%7}, {%8,%9}, {%0,%1,%2,%3};"
        : "+f"(d[0]), "+f"(d[1]), "+f"(d[2]), "+f"(d[3])
        : "r"(a[0]), "r"(a[1]), "r"(a[2]), "r"(a[3]), "r"(b0), "r"(b1));
}
__device__ __forceinline__ void cp16(uint32_t dst, const void* src, bool pred) {
    const int sz = pred ? 16 : 0;
    asm volatile("cp.async.cg.shared.global [%0], [%1], 16, %2;"
                 :: "r"(dst), "l"(src), "r"(sz) : "memory");
}
#define CP_COMMIT asm volatile("cp.async.commit_group;" ::: "memory")
#define CP_WAIT1  asm volatile("cp.async.wait_group 1;" ::: "memory")
#define CP_WAIT0  asm volatile("cp.async.wait_group 0;" ::: "memory")

// ---------------- conversion kernels ----------------
__global__ void convert_h_kernel(const float* __restrict__ h) {
    const int i = blockIdx.x * blockDim.x + threadIdx.x;
    if (i >= N_NODES * IN_F / 4) return;
    const float4 v = ((const float4*)h)[i];
    __nv_bfloat162 h01 = __floats2bfloat162_rn(v.x, v.y);
    __nv_bfloat162 h23 = __floats2bfloat162_rn(v.z, v.w);
    float2 f01 = __bfloat1622float2(h01);
    float2 f23 = __bfloat1622float2(h23);
    __nv_bfloat162 l01 = __floats2bfloat162_rn(v.x - f01.x, v.y - f01.y);
    __nv_bfloat162 l23 = __floats2bfloat162_rn(v.z - f23.x, v.w - f23.y);
    ((__nv_bfloat162*)g_Ahi)[2 * i]     = h01;
    ((__nv_bfloat162*)g_Ahi)[2 * i + 1] = h23;
    ((__nv_bfloat162*)g_Alo)[2 * i]     = l01;
    ((__nv_bfloat162*)g_Alo)[2 * i + 1] = l23;
}

// W [4096,1024] -> W^T hi/lo [1024,4096]
__global__ void convert_w_kernel(const float* __restrict__ W) {
    __shared__ float t[32][33];
    const int n0 = blockIdx.x * 32;
    const int k0 = blockIdx.y * 32;
    const int tx = threadIdx.x, ty = threadIdx.y;   // 32 x 8
    #pragma unroll
    for (int i = 0; i < 32; i += 8)
        t[ty + i][tx] = W[(size_t)(k0 + ty + i) * OUT_F + n0 + tx];
    __syncthreads();
    #pragma unroll
    for (int i = 0; i < 32; i += 8) {
        const float v = t[tx][ty + i];
        const __nv_bfloat16 hi = __float2bfloat16(v);
        const float lo = v - __bfloat162float(hi);
        const size_t o = (size_t)(n0 + ty + i) * IN_F + k0 + tx;
        g_Bhi[o] = hi;
        g_Blo[o] = __float2bfloat16(lo);
    }
}

// Wh [864,1024] -> Wh^T hi/lo [1024,896] (zero pad k>=864)
__global__ void wht_split_kernel() {
    __shared__ float t[32][33];
    const int n0 = blockIdx.x * 32;
    const int k0 = blockIdx.y * 32;
    const int tx = threadIdx.x, ty = threadIdx.y;   // 32 x 8
    #pragma unroll
    for (int i = 0; i < 32; i += 8) {
        const int k = k0 + ty + i;
        t[ty + i][tx] = (k < N_NODES) ? g_Wh[(size_t)k * OUT_F + n0 + tx] : 0.f;
    }
    __syncthreads();
    #pragma unroll
    for (int i = 0; i < 32; i += 8) {
        const float v = t[tx][ty + i];
        const __nv_bfloat16 hi = __float2bfloat16(v);
        const float lo = v - __bfloat162float(hi);
        const size_t o = (size_t)(n0 + ty + i) * K2PAD + k0 + tx;
        g_WThi[o] = hi;
        g_WTlo[o] = __float2bfloat16(lo);
    }
}

// fused = w0*att1 + w1*att2 -> A2 hi/lo [864,896] (zero pad)
__global__ void fuse_split_kernel() {
    const int r = blockIdx.x;
    const float w0 = g_wgt[0], w1 = g_wgt[1];
    for (int j = threadIdx.x; j < K2PAD; j += 256) {
        float f = 0.f;
        if (j < N_NODES)
            f = w0 * g_att1[(size_t)r * N_NODES + j] + w1 * g_att2[(size_t)r * N_NODES + j];
        const __nv_bfloat16 hi = __float2bfloat16(f);
        const float lo = f - __bfloat162float(hi);
        g_A2hi[(size_t)r * K2PAD + j] = hi;
        g_A2lo[(size_t)r * K2PAD + j] = __float2bfloat16(lo);
    }
}

// ---------------- unified mma GEMM: C[M,1024] = A[M,K] @ B^T ----------------
// ID=0: GEMM1 (A=g_Ahi/lo, B=g_Bhi/lo, LDK=4096, C=g_Wh,   no ELU)
// ID=1: GEMM2 (A=g_A2*,    B=g_WT*,   LDK=896,  C=out,     ELU)
// CTA tile 128x64, 8 warps, K-chunk 64, cp.async double-buffered (2x48KB).
template<int ID>
__global__ void __launch_bounds__(256, 1) gemm_mma_kernel(float* __restrict__ Cout,
                                                          int M, int NCH) {
    extern __shared__ __align__(1024) char smem[];
    const __nv_bfloat16* Ahi = (ID == 0) ? g_Ahi : g_A2hi;
    const __nv_bfloat16* Alo = (ID == 0) ? g_Alo : g_A2lo;
    const __nv_bfloat16* Bhi = (ID == 0) ? g_Bhi : g_WThi;
    const __nv_bfloat16* Blo = (ID == 0) ? g_Blo : g_WTlo;
    const int LDK = (ID == 0) ? IN_F : K2PAD;
    float* C = (ID == 0) ? g_Wh : Cout;

    const uint32_t sb = smem_u32(smem);
    const int tid  = threadIdx.x;
    const int lane = tid & 31;
    const int warp = tid >> 5;
    const int wm   = warp & 3;
    const int wn   = warp >> 2;
    const int bm = blockIdx.y * 128;
    const int bn = blockIdx.x * 64;
    const int mvalid = (M - bm < 128) ? (M - bm) : 128;

    float acc[2][4][4];
    #pragma unroll
    for (int mi = 0; mi < 2; mi++)
        #pragma unroll
        for (int nj = 0; nj < 4; nj++)
            #pragma unroll
            for (int q = 0; q < 4; q++) acc[mi][nj][q] = 0.f;

    const int a_r = ((lane >> 3) & 1) * 8 + (lane & 7);
    const int a_c = (lane >> 4) * 16;
    const int b_r = ((lane >> 4) & 1) * 8 + (lane & 7);
    const int b_c = ((lane >> 3) & 1) * 16;

    // ---- async stage of one chunk into buffer `buf`
    auto stage = [&](int buf, int chunk) {
        const uint32_t base = sb + buf * 49152;
        const int k0 = chunk * 64;
        #pragma unroll
        for (int it = 0; it < 4; it++) {
            const int s = tid + it * 256;
            const int r = s >> 3, cc = s & 7;
            const uint32_t off = SW128((uint32_t)(r * 128 + cc * 16));
            const bool ok = (r < mvalid);
            const size_t gi = (size_t)(bm + (ok ? r : 0)) * LDK + k0 + cc * 8;
            cp16(base + off,         Ahi + gi, ok);
            cp16(base + 16384 + off, Alo + gi, ok);
        }
        #pragma unroll
        for (int it = 0; it < 2; it++) {
            const int s = tid + it * 256;
            const int r = s >> 3, cc = s & 7;
            const uint32_t off = SW128((uint32_t)(r * 128 + cc * 16));
            const size_t gi = (size_t)(bn + r) * LDK + k0 + cc * 8;
            cp16(base + 32768 + off, Bhi + gi, true);
            cp16(base + 40960 + off, Blo + gi, true);
        }
        CP_COMMIT;
    };

    stage(0, 0);

    for (int c = 0; c < NCH; c++) {
        const int b = c & 1;
        if (c + 1 < NCH) { stage(b ^ 1, c + 1); CP_WAIT1; }
        else             { CP_WAIT0; }
        __syncthreads();

        const uint32_t base = sb + b * 49152;
        #pragma unroll
        for (int s = 0; s < 4; s++) {
            const int kb = s * 32;
            uint32_t ah[2][4], al[2][4];
            #pragma unroll
            for (int mi = 0; mi < 2; mi++) {
                const int row = wm * 32 + mi * 16 + a_r;
                const uint32_t co = (uint32_t)(kb + a_c) ^ (uint32_t)((row & 7) << 4);
                ldsm_x4(ah[mi], base + row * 128 + co);
                ldsm_x4(al[mi], base + 16384 + row * 128 + co);
            }
            uint32_t bh[2][4], bl[2][4];
            #pragma unroll
            for (int nj = 0; nj < 2; nj++) {
                const int row = wn * 32 + nj * 16 + b_r;
                const uint32_t co = (uint32_t)(kb + b_c) ^ (uint32_t)((row & 7) << 4);
                ldsm_x4(bh[nj], base + 32768 + row * 128 + co);
                ldsm_x4(bl[nj], base + 40960 + row * 128 + co);
            }
            #pragma unroll
            for (int mi = 0; mi < 2; mi++) {
                #pragma unroll
                for (int n8 = 0; n8 < 4; n8++) {
                    const int g = n8 >> 1, h = (n8 & 1) * 2;
                    mma_bf16(acc[mi][n8], ah[mi], bh[g][h], bh[g][h + 1]);
                    mma_bf16(acc[mi][n8], ah[mi], bl[g][h], bl[g][h + 1]);
                    mma_bf16(acc[mi][n8], al[mi], bh[g][h], bh[g][h + 1]);
                }
            }
        }
        __syncthreads();
    }

    // ---- epilogue
    #pragma unroll
    for (int mi = 0; mi < 2; mi++) {
        #pragma unroll
        for (int n8 = 0; n8 < 4; n8++) {
            const int row0 = bm + wm * 32 + mi * 16 + (lane >> 2);
            const int col  = bn + wn * 32 + n8 * 8 + (lane & 3) * 2;
            float v0 = acc[mi][n8][0], v1 = acc[mi][n8][1];
            float v2 = acc[mi][n8][2], v3 = acc[mi][n8][3];
            if (ID == 1) {
                v0 = v0 > 0.f ? v0 : expm1f(v0);
                v1 = v1 > 0.f ? v1 : expm1f(v1);
                v2 = v2 > 0.f ? v2 : expm1f(v2);
                v3 = v3 > 0.f ? v3 : expm1f(v3);
            }
            if (row0 < M)
                *(float2*)(C + (size_t)row0 * OUT_F + col) = make_float2(v0, v1);
            if (row0 + 8 < M)
                *(float2*)(C + (size_t)(row0 + 8) * OUT_F + col) = make_float2(v2, v3);
        }
    }
}

// ---------------- small kernels ----------------
__global__ void wh12_kernel(const float* __restrict__ a_vec) {
    const int i   = blockIdx.x;
    const int tid = threadIdx.x;
    float s1 = 0.f, s2 = 0.f;
    for (int c = tid; c < OUT_F; c += 256) {
        const float w = g_Wh[(size_t)i * OUT_F + c];
        s1 += w * a_vec[c];
        s2 += w * a_vec[OUT_F + c];
    }
    __shared__ float r1[256], r2[256];
    r1[tid] = s1; r2[tid] = s2;
    __syncthreads();
    for (int s = 128; s > 0; s >>= 1) {
        if (tid < s) { r1[tid] += r1[tid + s]; r2[tid] += r2[tid + s]; }
        __syncthreads();
    }
    if (tid == 0) { g_Wh1[i] = r1[0]; g_Wh2[i] = r2[0]; }
}

__global__ void attention_kernel(const int* __restrict__ adj1,
                                 const int* __restrict__ adj2) {
    const int i   = blockIdx.x;
    const int tid = threadIdx.x;
    __shared__ float l1s[N_NODES], l2s[N_NODES];
    __shared__ float red[256];
    const float wh1 = g_Wh1[i];
    float m1 = NEG_INF, m2 = NEG_INF;
    for (int j = tid; j < N_NODES; j += 256) {
        float e = wh1 + g_Wh2[j];
        e = (e > 0.f) ? e : ALPHA * e;
        const float l1 = (adj1[(size_t)i * N_NODES + j] > 0) ? e : NEG_INF;
        const float l2 = (adj2[(size_t)i * N_NODES + j] > 0) ? e : NEG_INF;
        l1s[j] = l1; l2s[j] = l2;
        m1 = fmaxf(m1, l1); m2 = fmaxf(m2, l2);
    }
    red[tid] = m1; __syncthreads();
    for (int s = 128; s > 0; s >>= 1) { if (tid < s) red[tid] = fmaxf(red[tid], red[tid + s]); __syncthreads(); }
    m1 = red[0]; __syncthreads();
    red[tid] = m2; __syncthreads();
    for (int s = 128; s > 0; s >>= 1) { if (tid < s) red[tid] = fmaxf(red[tid], red[tid + s]); __syncthreads(); }
    m2 = red[0]; __syncthreads();
    float s1 = 0.f, s2 = 0.f;
    for (int j = tid; j < N_NODES; j += 256) {
        s1 += expf(l1s[j] - m1);
        s2 += expf(l2s[j] - m2);
    }
    red[tid] = s1; __syncthreads();
    for (int s = 128; s > 0; s >>= 1) { if (tid < s) red[tid] += red[tid + s]; __syncthreads(); }
    s1 = red[0]; __syncthreads();
    red[tid] = s2; __syncthreads();
    for (int s = 128; s > 0; s >>= 1) { if (tid < s) red[tid] += red[tid + s]; __syncthreads(); }
    s2 = red[0]; __syncthreads();
    const float inv1 = 1.f / s1;
    const float inv2 = 1.f / s2;
    for (int j = tid; j < N_NODES; j += 256) {
        g_att1[(size_t)i * N_NODES + j] = expf(l1s[j] - m1) * inv1;
        g_att2[(size_t)i * N_NODES + j] = expf(l2s[j] - m2) * inv2;
    }
}

__global__ void pool_max_kernel() {
    const int warp = (blockIdx.x << 3) + (threadIdx.x >> 5);
    if (warp >= 2 * NWIN) return;
    const int lane = threadIdx.x & 31;
    const int m  = warp / NWIN;
    const int w  = warp - m * NWIN;
    const int wr = w / NPOOL;
    const int wc = w - wr * NPOOL;
    const float* __restrict__ att = (m == 0) ? g_att1 : g_att2;
    const float* base = att + (size_t)(wr * 16) * N_NODES + wc * 16;
    float mx = -INFINITY;
    #pragma unroll
    for (int it = 0; it < 8; it++) {
        const int idx = lane + (it << 5);
        const int r = idx >> 4;
        const int c = idx & 15;
        mx = fmaxf(mx, base[(size_t)r * N_NODES + c]);
    }
    #pragma unroll
    for (int s = 16; s > 0; s >>= 1)
        mx = fmaxf(mx, __shfl_xor_sync(0xffffffffu, mx, s));
    if (lane == 0) g_pooled[warp] = mx;
}

__global__ void logits_kernel(const float* __restrict__ L_w,
                              const float* __restrict__ L_b) {
    const int m   = blockIdx.x;
    const int tid = threadIdx.x;
    float acc = 0.f;
    for (int i = tid; i < NWIN; i += 1024)
        acc += g_pooled[m * NWIN + i] * L_w[i];
    __shared__ float red[1024];
    red[tid] = acc;
    __syncthreads();
    for (int s = 512; s > 0; s >>= 1) {
        if (tid < s) red[tid] += red[tid + s];
        __syncthreads();
    }
    if (tid == 0) g_logits[m] = red[0] + L_b[0];
}

__global__ void wgt_kernel() {
    float l0 = g_logits[0];
    float l1 = g_logits[1];
    l0 = (l0 > 0.f) ? l0 : ALPHA * l0;
    l1 = (l1 > 0.f) ? l1 : ALPHA * l1;
    const float mx = fmaxf(l0, l1);
    const float e0 = expf(l0 - mx);
    const float e1 = expf(l1 - mx);
    const float inv = 1.f / (e0 + e1);
    g_wgt[0] = e0 * inv;
    g_wgt[1] = e1 * inv;
}

// ---------------- launch ----------------
extern "C" void kernel_launch(void* const* d_in, const int* in_sizes, int n_in,
                              void* d_out, int out_size) {
    const float* h    = (const float*)d_in[0];
    const int*   adj1 = (const int*)d_in[2];
    const int*   adj2 = (const int*)d_in[3];
    const float* W    = (const float*)d_in[4];
    const float* a    = (const float*)d_in[5];
    const float* L_w  = (const float*)d_in[6];
    const float* L_b  = (const float*)d_in[7];
    float* out = (float*)d_out;

    const int GSMEM = 2 * 49152;
    cudaFuncSetAttribute(gemm_mma_kernel<0>, cudaFuncAttributeMaxDynamicSharedMemorySize, GSMEM);
    cudaFuncSetAttribute(gemm_mma_kernel<1>, cudaFuncAttributeMaxDynamicSharedMemorySize, GSMEM);
    const dim3 ggrid(OUT_F / 64, (N_NODES + 127) / 128);   // (16, 7)

    // 0. split conversions
    convert_h_kernel<<<(N_NODES * IN_F / 4 + 255) / 256, 256>>>(h);
    convert_w_kernel<<<dim3(OUT_F / 32, IN_F / 32), dim3(32, 8)>>>(W);
    // 1. Wh = h @ W
    gemm_mma_kernel<0><<<ggrid, 256, GSMEM>>>(nullptr, N_NODES, IN_F / 64);
    // 2. Wh1/Wh2 row dots  +  Wh^T split for GEMM2
    wh12_kernel<<<N_NODES, 256>>>(a);
    wht_split_kernel<<<dim3(OUT_F / 32, K2PAD / 32), dim3(32, 8)>>>();
    // 3. attention logits + masked softmaxes
    attention_kernel<<<N_NODES, 256>>>(adj1, adj2);
    // 4. 16x16 maxpool
    pool_max_kernel<<<(2 * NWIN + 7) / 8, 256>>>();
    // 5. pooled . L_w + b per map
    logits_kernel<<<2, 1024>>>(L_w, L_b);
    // 6. fusion weights
    wgt_kernel<<<1, 1>>>();
    // 7. fused att -> bf16 split
    fuse_split_kernel<<<N_NODES, 256>>>();
    // 8. out = elu( fused @ Wh )
    gemm_mma_kernel<1><<<ggrid, 256, GSMEM>>>(out, N_NODES, K2PAD / 64);
}